// round 7
// baseline (speedup 1.0000x reference)
#include <cuda_runtime.h>
#include <cuda_bf16.h>
#include <cstdint>
#include <cstddef>

#define T_STEPS 16
#define B_SIZE  16384
#define DIN     64
#define DH      256
#define DMID    64
#define DOUT    4
#define M_CTA   32
#define NCTAS   (B_SIZE / M_CTA)   // 512
#define NTH     256

#define HKP 128   // h k-pairs per row
#define XKP 32    // x k-pairs per row

// SMEM word offsets (52 KB/CTA -> 4 CTAs/SM)
#define H1_OFF   0
#define H2_OFF   (H1_OFF + M_CTA * HKP)     // 4096
#define X1_OFF   (H2_OFF + M_CTA * HKP)     // 8192
#define X2_OFF   (X1_OFF + M_CTA * XKP)     // 9216
#define SMS_OFF  (X2_OFF + M_CTA * XKP)     // 10240 : mid f32 [32][68]
#define WFC_OFF  (SMS_OFF + M_CTA * 68)     // 12416
#define BH2O_OFF (WFC_OFF + 4 * 65)
#define BFC_OFF  (BH2O_OFF + 64)
#define BSUM_OFF (BFC_OFF + 4)
#define SMEM_WORDS (BSUM_OFF + 256)
#define SMEM_BYTES (SMEM_WORDS * 4)

// One flat weight array -> single base pointer in the kernel
#define W1OFF  0                 // GEMM1 hi split [kk<20][w<8][p<2][lane][4]
#define W2OFF  40960             // GEMM1 lo split
#define WO1OFF 81920             // GEMM2 hi split [kk<16][wn<4][lane][4]
#define WO2OFF 90112             // GEMM2 lo split
#define WALL_WORDS 98304
__device__ uint32_t g_Wall[WALL_WORDS];
__device__ float g_bsum[DH];

__device__ __forceinline__ uint32_t pk(__nv_bfloat16 lo, __nv_bfloat16 hi) {
    return (uint32_t)__bfloat16_as_ushort(lo) | ((uint32_t)__bfloat16_as_ushort(hi) << 16);
}
__device__ __forceinline__ int hidx(int row, int kp) { return row * HKP + (kp ^ ((row & 7) << 2)); }
__device__ __forceinline__ int xidx(int row, int kp) { return row * XKP + (kp ^ ((row & 7) << 2)); }

#define MMA(d, A0, A1_, A2_, A3_, b0, b1)                                         \
    asm volatile("mma.sync.aligned.m16n8k16.row.col.f32.bf16.bf16.f32 "           \
                 "{%0,%1,%2,%3},{%4,%5,%6,%7},{%8,%9},{%0,%1,%2,%3};"             \
                 : "+f"(d[0]), "+f"(d[1]), "+f"(d[2]), "+f"(d[3])                 \
                 : "r"(A0), "r"(A1_), "r"(A2_), "r"(A3_), "r"(b0), "r"(b1))

#define LDSM4(a0, a1, a2, a3, addr)                                               \
    asm volatile("ldmatrix.sync.aligned.m8n8.x4.shared.b16 {%0,%1,%2,%3}, [%4];"  \
                 : "=r"(a0), "=r"(a1), "=r"(a2), "=r"(a3) : "r"(addr))

// byte addr of A fragment: base + mt row-block + swizzled k-chunk
#define AH(base, mt, kp0) ((base) + (mt) * (16 * HKP * 4) + (((((kp0) + kadd)) ^ sxor) << 2))
#define AX(base, mt, kp0) ((base) + (mt) * (16 * XKP * 4) + (((((kp0) + kadd)) ^ sxor) << 2))

__global__ void prep_kernel(const float* __restrict__ Wi2h,
                            const float* __restrict__ bi2h,
                            const float* __restrict__ Wh2h,
                            const float* __restrict__ bh2h,
                            const float* __restrict__ Wh2o) {
    const int stride = gridDim.x * blockDim.x;
    const int tid = blockIdx.x * blockDim.x + threadIdx.x;
    for (int i = tid; i < 40960; i += stride) {
        int word = i & 3, lane = (i >> 2) & 31, p = (i >> 7) & 1, w = (i >> 8) & 7, kk = i >> 11;
        int gg = lane >> 2, tt = lane & 3;
        int n = w * 32 + p * 16 + ((word >> 1) ? 8 : 0) + gg;
        int k = kk * 16 + tt * 2 + ((word & 1) ? 8 : 0);
        float v0, v1;
        if (k < DIN) { v0 = Wi2h[n * DIN + k]; v1 = Wi2h[n * DIN + k + 1]; }
        else         { v0 = Wh2h[n * DH + k - DIN]; v1 = Wh2h[n * DH + k - DIN + 1]; }
        __nv_bfloat16 h0 = __float2bfloat16_rn(v0), h1 = __float2bfloat16_rn(v1);
        g_Wall[W1OFF + i] = pk(h0, h1);
        g_Wall[W2OFF + i] = pk(__float2bfloat16_rn(v0 - __bfloat162float(h0)),
                               __float2bfloat16_rn(v1 - __bfloat162float(h1)));
    }
    for (int i = tid; i < 8192; i += stride) {
        int word = i & 3, lane = (i >> 2) & 31, wn = (i >> 7) & 3, kk = i >> 9;
        int gg = lane >> 2, tt = lane & 3;
        int n = wn * 16 + ((word >> 1) ? 8 : 0) + gg;
        int k = kk * 16 + tt * 2 + ((word & 1) ? 8 : 0);
        float v0 = Wh2o[n * DH + k], v1 = Wh2o[n * DH + k + 1];
        __nv_bfloat16 h0 = __float2bfloat16_rn(v0), h1 = __float2bfloat16_rn(v1);
        g_Wall[WO1OFF + i] = pk(h0, h1);
        g_Wall[WO2OFF + i] = pk(__float2bfloat16_rn(v0 - __bfloat162float(h0)),
                                __float2bfloat16_rn(v1 - __bfloat162float(h1)));
    }
    for (int i = tid; i < DH; i += stride) g_bsum[i] = bi2h[i] + bh2h[i];
}

__global__ void __launch_bounds__(NTH, 4)
rnn_kernel(const float* __restrict__ x,
           const float* __restrict__ hc1,
           const float* __restrict__ Wfc,
           const float* __restrict__ bh2o,
           const float* __restrict__ bfc,
           float* __restrict__ out) {
    extern __shared__ uint32_t sm[];
    float* smf = (float*)sm;
    uint32_t* H1 = sm + H1_OFF;
    uint32_t* H2 = sm + H2_OFF;
    uint32_t* X1 = sm + X1_OFF;
    uint32_t* X2 = sm + X2_OFF;

    const int tid = threadIdx.x, w = tid >> 5, lane = tid & 31;
    const int g = lane >> 2, t = lane & 3;
    const int wn = w & 3, mh = (w >> 2) & 1;
    const int gbase = blockIdx.x * M_CTA;

    // ldmatrix per-thread geometry
    const int rowA = (lane & 7) + ((lane >> 3) & 1) * 8;
    const uint32_t kadd = (lane >> 4) * 4;
    const uint32_t sxor = (uint32_t)((lane & 7) << 2);

    const uint32_t h1b = (uint32_t)__cvta_generic_to_shared(H1 + rowA * HKP);
    const uint32_t h2b = (uint32_t)__cvta_generic_to_shared(H2 + rowA * HKP);
    const uint32_t x1b = (uint32_t)__cvta_generic_to_shared(X1 + rowA * XKP);
    const uint32_t x2b = (uint32_t)__cvta_generic_to_shared(X2 + rowA * XKP);

    { // constants
        int c = tid >> 6, k = tid & 63;
        smf[WFC_OFF + c * 65 + k] = Wfc[c * DMID + k];
        if (tid < DMID) smf[BH2O_OFF + tid] = bh2o[tid];
        if (tid < DOUT) smf[BFC_OFF + tid] = bfc[tid];
        smf[BSUM_OFF + tid] = g_bsum[tid];
    }
    // stage hc1 split into H1/H2 (32 rows x 128 kp)
    for (int i = tid; i < M_CTA * HKP; i += NTH) {
        int row = i >> 7, kp = i & 127;
        float2 v = *(const float2*)(hc1 + (size_t)(gbase + row) * DH + kp * 2);
        __nv_bfloat16 b0 = __float2bfloat16_rn(v.x), b1 = __float2bfloat16_rn(v.y);
        H1[hidx(row, kp)] = pk(b0, b1);
        H2[hidx(row, kp)] = pk(__float2bfloat16_rn(v.x - __bfloat162float(b0)),
                               __float2bfloat16_rn(v.y - __bfloat162float(b1)));
    }
    __syncthreads();

    // per-warp weight word offsets into g_Wall
    const int w1o = W1OFF + w * 256 + lane * 4;     // +kk*2048, B1 at +128
    const int w2o = W2OFF + w * 256 + lane * 4;
    const int wo1 = WO1OFF + wn * 128 + lane * 4;   // +kk*512
    const int wo2 = WO2OFF + wn * 128 + lane * 4;

    float* outseq = out;
    float* hfin = out + (size_t)T_STEPS * B_SIZE * DOUT;

    for (int ts = 0; ts < T_STEPS; ++ts) {
        // ---- stage x split (32 rows x 32 kp) ----
        const float* xt = x + ((size_t)ts * B_SIZE + gbase) * DIN;
        for (int i = tid; i < M_CTA * XKP; i += NTH) {
            int row = i >> 5, kp = i & 31;
            float2 v = *(const float2*)(xt + (size_t)row * DIN + kp * 2);
            __nv_bfloat16 b0 = __float2bfloat16_rn(v.x), b1 = __float2bfloat16_rn(v.y);
            X1[xidx(row, kp)] = pk(b0, b1);
            X2[xidx(row, kp)] = pk(__float2bfloat16_rn(v.x - __bfloat162float(b0)),
                                   __float2bfloat16_rn(v.y - __bfloat162float(b1)));
        }
        __syncthreads();   // [A]

        // ---- GEMM1: warp = 32-col n-slice, 2 m-tiles ----
        float acc[2][4][4];
        #pragma unroll
        for (int nt = 0; nt < 4; ++nt) {
            int n0 = w * 32 + nt * 8 + 2 * t;
            float b0 = smf[BSUM_OFF + n0], b1 = smf[BSUM_OFF + n0 + 1];
            #pragma unroll
            for (int mt = 0; mt < 2; ++mt) {
                acc[mt][nt][0] = b0; acc[mt][nt][1] = b1;
                acc[mt][nt][2] = b0; acc[mt][nt][3] = b1;
            }
        }

        // pass 1 (W1): x part then h part, A1 and A2
        #pragma unroll
        for (int kk = 0; kk < 4; ++kk) {
            uint4 B0 = *(const uint4*)(g_Wall + w1o + kk * 2048);
            uint4 B1 = *(const uint4*)(g_Wall + w1o + kk * 2048 + 128);
            uint32_t a0, a1, a2, a3;
            #pragma unroll
            for (int mt = 0; mt < 2; ++mt) {
                LDSM4(a0, a1, a2, a3, AX(x1b, mt, kk * 8));
                MMA(acc[mt][0], a0, a1, a2, a3, B0.x, B0.y);
                MMA(acc[mt][1], a0, a1, a2, a3, B0.z, B0.w);
                MMA(acc[mt][2], a0, a1, a2, a3, B1.x, B1.y);
                MMA(acc[mt][3], a0, a1, a2, a3, B1.z, B1.w);
                LDSM4(a0, a1, a2, a3, AX(x2b, mt, kk * 8));
                MMA(acc[mt][0], a0, a1, a2, a3, B0.x, B0.y);
                MMA(acc[mt][1], a0, a1, a2, a3, B0.z, B0.w);
                MMA(acc[mt][2], a0, a1, a2, a3, B1.x, B1.y);
                MMA(acc[mt][3], a0, a1, a2, a3, B1.z, B1.w);
            }
        }
        #pragma unroll 4
        for (int kk = 4; kk < 20; ++kk) {
            uint4 B0 = *(const uint4*)(g_Wall + w1o + kk * 2048);
            uint4 B1 = *(const uint4*)(g_Wall + w1o + kk * 2048 + 128);
            uint32_t a0, a1, a2, a3;
            const uint32_t kp0 = (kk - 4) * 8;
            #pragma unroll
            for (int mt = 0; mt < 2; ++mt) {
                LDSM4(a0, a1, a2, a3, AH(h1b, mt, kp0));
                MMA(acc[mt][0], a0, a1, a2, a3, B0.x, B0.y);
                MMA(acc[mt][1], a0, a1, a2, a3, B0.z, B0.w);
                MMA(acc[mt][2], a0, a1, a2, a3, B1.x, B1.y);
                MMA(acc[mt][3], a0, a1, a2, a3, B1.z, B1.w);
                LDSM4(a0, a1, a2, a3, AH(h2b, mt, kp0));
                MMA(acc[mt][0], a0, a1, a2, a3, B0.x, B0.y);
                MMA(acc[mt][1], a0, a1, a2, a3, B0.z, B0.w);
                MMA(acc[mt][2], a0, a1, a2, a3, B1.x, B1.y);
                MMA(acc[mt][3], a0, a1, a2, a3, B1.z, B1.w);
            }
        }
        // pass 2 (W2): A1 only
        #pragma unroll
        for (int kk = 0; kk < 4; ++kk) {
            uint4 B0 = *(const uint4*)(g_Wall + w2o + kk * 2048);
            uint4 B1 = *(const uint4*)(g_Wall + w2o + kk * 2048 + 128);
            uint32_t a0, a1, a2, a3;
            #pragma unroll
            for (int mt = 0; mt < 2; ++mt) {
                LDSM4(a0, a1, a2, a3, AX(x1b, mt, kk * 8));
                MMA(acc[mt][0], a0, a1, a2, a3, B0.x, B0.y);
                MMA(acc[mt][1], a0, a1, a2, a3, B0.z, B0.w);
                MMA(acc[mt][2], a0, a1, a2, a3, B1.x, B1.y);
                MMA(acc[mt][3], a0, a1, a2, a3, B1.z, B1.w);
            }
        }
        #pragma unroll 4
        for (int kk = 4; kk < 20; ++kk) {
            uint4 B0 = *(const uint4*)(g_Wall + w2o + kk * 2048);
            uint4 B1 = *(const uint4*)(g_Wall + w2o + kk * 2048 + 128);
            uint32_t a0, a1, a2, a3;
            #pragma unroll
            for (int mt = 0; mt < 2; ++mt) {
                LDSM4(a0, a1, a2, a3, AH(h1b, mt, (kk - 4) * 8));
                MMA(acc[mt][0], a0, a1, a2, a3, B0.x, B0.y);
                MMA(acc[mt][1], a0, a1, a2, a3, B0.z, B0.w);
                MMA(acc[mt][2], a0, a1, a2, a3, B1.x, B1.y);
                MMA(acc[mt][3], a0, a1, a2, a3, B1.z, B1.w);
            }
        }

        __syncthreads();   // [B]

        // ---- GEMM1 epilogue: tanh, split, write H1/H2 ----
        #pragma unroll
        for (int mt = 0; mt < 2; ++mt)
            #pragma unroll
            for (int nt = 0; nt < 4; ++nt) {
                float v0 = tanhf(acc[mt][nt][0]), v1 = tanhf(acc[mt][nt][1]);
                float v2 = tanhf(acc[mt][nt][2]), v3 = tanhf(acc[mt][nt][3]);
                int kp = w * 16 + nt * 4 + t;
                int r0 = mt * 16 + g, r1 = r0 + 8;
                __nv_bfloat16 c0 = __float2bfloat16_rn(v0), c1 = __float2bfloat16_rn(v1);
                __nv_bfloat16 c2 = __float2bfloat16_rn(v2), c3 = __float2bfloat16_rn(v3);
                H1[hidx(r0, kp)] = pk(c0, c1);
                H1[hidx(r1, kp)] = pk(c2, c3);
                H2[hidx(r0, kp)] = pk(__float2bfloat16_rn(v0 - __bfloat162float(c0)),
                                      __float2bfloat16_rn(v1 - __bfloat162float(c1)));
                H2[hidx(r1, kp)] = pk(__float2bfloat16_rn(v2 - __bfloat162float(c2)),
                                      __float2bfloat16_rn(v3 - __bfloat162float(c3)));
            }
        __syncthreads();   // [C]

        // ---- GEMM2: warp = (mh m-tile, wn 16-col slice) ----
        float acc2[2][4];
        #pragma unroll
        for (int nt = 0; nt < 2; ++nt) {
            int n0 = wn * 16 + nt * 8 + 2 * t;
            float b0 = smf[BH2O_OFF + n0], b1 = smf[BH2O_OFF + n0 + 1];
            acc2[nt][0] = b0; acc2[nt][1] = b1; acc2[nt][2] = b0; acc2[nt][3] = b1;
        }
        #pragma unroll 4
        for (int kk = 0; kk < 16; ++kk) {
            uint4 B0 = *(const uint4*)(g_Wall + wo1 + kk * 512);
            uint32_t a0, a1, a2, a3;
            LDSM4(a0, a1, a2, a3, AH(h1b, mh, kk * 8));
            MMA(acc2[0], a0, a1, a2, a3, B0.x, B0.y);
            MMA(acc2[1], a0, a1, a2, a3, B0.z, B0.w);
            LDSM4(a0, a1, a2, a3, AH(h2b, mh, kk * 8));
            MMA(acc2[0], a0, a1, a2, a3, B0.x, B0.y);
            MMA(acc2[1], a0, a1, a2, a3, B0.z, B0.w);
        }
        #pragma unroll 4
        for (int kk = 0; kk < 16; ++kk) {
            uint4 B0 = *(const uint4*)(g_Wall + wo2 + kk * 512);
            uint32_t a0, a1, a2, a3;
            LDSM4(a0, a1, a2, a3, AH(h1b, mh, kk * 8));
            MMA(acc2[0], a0, a1, a2, a3, B0.x, B0.y);
            MMA(acc2[1], a0, a1, a2, a3, B0.z, B0.w);
        }
        #pragma unroll
        for (int nt = 0; nt < 2; ++nt) {
            int n0 = wn * 16 + nt * 8 + 2 * t;
            int r0 = mh * 16 + g, r1 = r0 + 8;
            smf[SMS_OFF + r0 * 68 + n0]     = tanhf(acc2[nt][0]);
            smf[SMS_OFF + r0 * 68 + n0 + 1] = tanhf(acc2[nt][1]);
            smf[SMS_OFF + r1 * 68 + n0]     = tanhf(acc2[nt][2]);
            smf[SMS_OFF + r1 * 68 + n0 + 1] = tanhf(acc2[nt][3]);
        }
        __syncthreads();   // [D]

        // ---- GEMM3: rows 0..31, threads 0..127 ----
        if (tid < M_CTA * DOUT) {
            const int row = tid >> 2, col = tid & 3;
            float a3 = smf[BFC_OFF + col];
            const float* mrow = &smf[SMS_OFF + row * 68];
            const float* wrow = &smf[WFC_OFF + col * 65];
            #pragma unroll 8
            for (int k = 0; k < DMID; ++k)
                a3 = fmaf(mrow[k], wrow[k], a3);
            outseq[((size_t)ts * B_SIZE + gbase + row) * DOUT + col] = a3;
        }
    }

    __syncthreads();
    // ---- h_final = H1 + H2 ----
    for (int i = tid; i < M_CTA * HKP; i += NTH) {
        int row = i >> 7, kp = i & 127;
        uint32_t w1 = H1[hidx(row, kp)], w2 = H2[hidx(row, kp)];
        float2 v;
        v.x = __bfloat162float(__ushort_as_bfloat16((unsigned short)(w1 & 0xFFFF))) +
              __bfloat162float(__ushort_as_bfloat16((unsigned short)(w2 & 0xFFFF)));
        v.y = __bfloat162float(__ushort_as_bfloat16((unsigned short)(w1 >> 16))) +
              __bfloat162float(__ushort_as_bfloat16((unsigned short)(w2 >> 16)));
        *(float2*)(hfin + (size_t)(gbase + row) * DH + kp * 2) = v;
    }
}

extern "C" void kernel_launch(void* const* d_in, const int* in_sizes, int n_in,
                              void* d_out, int out_size) {
    const float* x    = (const float*)d_in[0];
    const float* hc1  = (const float*)d_in[1];
    const float* Wi2h = (const float*)d_in[2];
    const float* bi2h = (const float*)d_in[3];
    const float* Wh2h = (const float*)d_in[4];
    const float* bh2h = (const float*)d_in[5];
    const float* Wh2o = (const float*)d_in[6];
    const float* bh2o = (const float*)d_in[7];
    const float* Wfc  = (const float*)d_in[8];
    const float* bfc  = (const float*)d_in[9];
    float* out = (float*)d_out;

    cudaFuncSetAttribute(rnn_kernel, cudaFuncAttributeMaxDynamicSharedMemorySize, SMEM_BYTES);

    prep_kernel<<<64, 256>>>(Wi2h, bi2h, Wh2h, bh2h, Wh2o);
    rnn_kernel<<<NCTAS, NTH, SMEM_BYTES>>>(x, hc1, Wfc, bh2o, bfc, out);
}

// round 8
// speedup vs baseline: 1.1141x; 1.1141x over previous
#include <cuda_runtime.h>
#include <cuda_bf16.h>
#include <cstdint>
#include <cstddef>

#define T_STEPS 16
#define B_SIZE  16384
#define DIN     64
#define DH      256
#define DMID    64
#define DOUT    4
#define M_CTA   64
#define NCTAS   (B_SIZE / M_CTA)   // 256
#define NTH     256

#define HKP 128   // h k-pairs per row
#define XKP 32    // x k-pairs per row

// SMEM word offsets
#define H1_OFF   0
#define H2_OFF   (H1_OFF + 64 * HKP)
#define X1_OFF   (H2_OFF + 64 * HKP)
#define X2_OFF   (X1_OFF + 64 * XKP)
#define SMS_OFF  (X2_OFF + 64 * XKP)      // mid f32 [64][68]
#define WFC_OFF  (SMS_OFF + 64 * 68)
#define BH2O_OFF (WFC_OFF + 4 * 65)
#define BFC_OFF  (BH2O_OFF + 64)
#define BSUM_OFF (BFC_OFF + 4)
#define SMEM_WORDS (BSUM_OFF + 256)
#define SMEM_BYTES (SMEM_WORDS * 4)

// Pre-packed weight fragments (u32 = 2 bf16), +1 kk pad for prefetch clamp safety
__device__ uint32_t g_W1[21 * 8 * 2 * 32 * 4];   // GEMM1 hi split [kk][w][p][lane][4]
__device__ uint32_t g_W2[21 * 8 * 2 * 32 * 4];   // GEMM1 lo split
__device__ uint32_t g_Wo1[17 * 4 * 32 * 4];      // GEMM2 hi split [kk][wn][lane][4]
__device__ uint32_t g_Wo2[17 * 4 * 32 * 4];
__device__ float g_bsum[DH];

__device__ __forceinline__ uint32_t pk(__nv_bfloat16 lo, __nv_bfloat16 hi) {
    return (uint32_t)__bfloat16_as_ushort(lo) | ((uint32_t)__bfloat16_as_ushort(hi) << 16);
}
__device__ __forceinline__ int hidx(int row, int kp) { return row * HKP + (kp ^ ((row & 7) << 2)); }
__device__ __forceinline__ int xidx(int row, int kp) { return row * XKP + (kp ^ ((row & 7) << 2)); }

// fast accurate tanh: 1 - 2/(e^{2x}+1); abs err ~1e-6, saturates correctly
__device__ __forceinline__ float ftanh(float x) {
    float t = __expf(2.0f * x);
    float r;
    asm("rcp.approx.f32 %0, %1;" : "=f"(r) : "f"(t + 1.0f));
    return fmaf(-2.0f, r, 1.0f);
}

// split (v0,v1) -> hi word (bf16x2) + lo residual word (bf16x2)
__device__ __forceinline__ void split2(float v0, float v1, uint32_t& hi, uint32_t& lo) {
    asm("cvt.rn.bf16x2.f32 %0, %1, %2;" : "=r"(hi) : "f"(v1), "f"(v0));
    float f0 = __uint_as_float(hi << 16);
    float f1 = __uint_as_float(hi & 0xFFFF0000u);
    float r0 = v0 - f0, r1 = v1 - f1;
    asm("cvt.rn.bf16x2.f32 %0, %1, %2;" : "=r"(lo) : "f"(r1), "f"(r0));
}

#define MMA(d, A0, A1_, A2_, A3_, b0, b1)                                         \
    asm volatile("mma.sync.aligned.m16n8k16.row.col.f32.bf16.bf16.f32 "           \
                 "{%0,%1,%2,%3},{%4,%5,%6,%7},{%8,%9},{%0,%1,%2,%3};"             \
                 : "+f"(d[0]), "+f"(d[1]), "+f"(d[2]), "+f"(d[3])                 \
                 : "r"(A0), "r"(A1_), "r"(A2_), "r"(A3_), "r"(b0), "r"(b1))

#define LDSM4(a0, a1, a2, a3, addr)                                               \
    asm volatile("ldmatrix.sync.aligned.m8n8.x4.shared.b16 {%0,%1,%2,%3}, [%4];"  \
                 : "=r"(a0), "=r"(a1), "=r"(a2), "=r"(a3) : "r"(addr))

#define AH(base, mt, kp0) ((base) + (mt) * (16 * HKP * 4) + (((((kp0) + kadd)) ^ sxor) << 2))
#define AX(base, mt, kp0) ((base) + (mt) * (16 * XKP * 4) + (((((kp0) + kadd)) ^ sxor) << 2))

__global__ void prep_kernel(const float* __restrict__ Wi2h,
                            const float* __restrict__ bi2h,
                            const float* __restrict__ Wh2h,
                            const float* __restrict__ bh2h,
                            const float* __restrict__ Wh2o) {
    const int stride = gridDim.x * blockDim.x;
    const int tid = blockIdx.x * blockDim.x + threadIdx.x;
    for (int i = tid; i < 20 * 8 * 2 * 32 * 4; i += stride) {
        int word = i & 3, lane = (i >> 2) & 31, p = (i >> 7) & 1, w = (i >> 8) & 7, kk = i >> 11;
        int gg = lane >> 2, tt = lane & 3;
        int n = w * 32 + p * 16 + ((word >> 1) ? 8 : 0) + gg;
        int k = kk * 16 + tt * 2 + ((word & 1) ? 8 : 0);
        float v0, v1;
        if (k < DIN) { v0 = Wi2h[n * DIN + k]; v1 = Wi2h[n * DIN + k + 1]; }
        else         { v0 = Wh2h[n * DH + k - DIN]; v1 = Wh2h[n * DH + k - DIN + 1]; }
        __nv_bfloat16 h0 = __float2bfloat16_rn(v0), h1 = __float2bfloat16_rn(v1);
        g_W1[i] = pk(h0, h1);
        g_W2[i] = pk(__float2bfloat16_rn(v0 - __bfloat162float(h0)),
                     __float2bfloat16_rn(v1 - __bfloat162float(h1)));
    }
    for (int i = tid; i < 16 * 4 * 32 * 4; i += stride) {
        int word = i & 3, lane = (i >> 2) & 31, wn = (i >> 7) & 3, kk = i >> 9;
        int gg = lane >> 2, tt = lane & 3;
        int n = wn * 16 + ((word >> 1) ? 8 : 0) + gg;
        int k = kk * 16 + tt * 2 + ((word & 1) ? 8 : 0);
        float v0 = Wh2o[n * DH + k], v1 = Wh2o[n * DH + k + 1];
        __nv_bfloat16 h0 = __float2bfloat16_rn(v0), h1 = __float2bfloat16_rn(v1);
        g_Wo1[i] = pk(h0, h1);
        g_Wo2[i] = pk(__float2bfloat16_rn(v0 - __bfloat162float(h0)),
                      __float2bfloat16_rn(v1 - __bfloat162float(h1)));
    }
    for (int i = tid; i < DH; i += stride) g_bsum[i] = bi2h[i] + bh2h[i];
}

__global__ void __launch_bounds__(NTH, 2)
rnn_kernel(const float* __restrict__ x,
           const float* __restrict__ hc1,
           const float* __restrict__ Wfc,
           const float* __restrict__ bh2o,
           const float* __restrict__ bfc,
           float* __restrict__ out) {
    extern __shared__ uint32_t sm[];
    float* smf = (float*)sm;
    uint32_t* H1 = sm + H1_OFF;
    uint32_t* H2 = sm + H2_OFF;
    uint32_t* X1 = sm + X1_OFF;
    uint32_t* X2 = sm + X2_OFF;

    const int tid = threadIdx.x, w = tid >> 5, lane = tid & 31;
    const int g = lane >> 2, t = lane & 3;
    const int wn = w & 3, mh = w >> 2;
    const int gbase = blockIdx.x * M_CTA;

    const int rowA = (lane & 7) + ((lane >> 3) & 1) * 8;
    const uint32_t kadd = (lane >> 4) * 4;
    const uint32_t sxor = (uint32_t)((lane & 7) << 2);

    const uint32_t h1b = (uint32_t)__cvta_generic_to_shared(H1 + rowA * HKP);
    const uint32_t h2b = (uint32_t)__cvta_generic_to_shared(H2 + rowA * HKP);
    const uint32_t x1b = (uint32_t)__cvta_generic_to_shared(X1 + rowA * XKP);
    const uint32_t x2b = (uint32_t)__cvta_generic_to_shared(X2 + rowA * XKP);

    { // constants
        int c = tid >> 6, k = tid & 63;
        smf[WFC_OFF + c * 65 + k] = Wfc[c * DMID + k];
        if (tid < DMID) smf[BH2O_OFF + tid] = bh2o[tid];
        if (tid < DOUT) smf[BFC_OFF + tid] = bfc[tid];
        smf[BSUM_OFF + tid] = g_bsum[tid];
    }
    // stage hc1 split into H1/H2
    for (int i = tid; i < 64 * HKP; i += NTH) {
        int row = i >> 7, kp = i & 127;
        float2 v = *(const float2*)(hc1 + (size_t)(gbase + row) * DH + kp * 2);
        uint32_t hi, lo;
        split2(v.x, v.y, hi, lo);
        H1[hidx(row, kp)] = hi;
        H2[hidx(row, kp)] = lo;
    }
    __syncthreads();

    float bias1[4][2], bias2[2][2];
    #pragma unroll
    for (int nt = 0; nt < 4; ++nt) {
        int n0 = w * 32 + nt * 8 + 2 * t;
        bias1[nt][0] = smf[BSUM_OFF + n0]; bias1[nt][1] = smf[BSUM_OFF + n0 + 1];
    }
    #pragma unroll
    for (int nt = 0; nt < 2; ++nt) {
        int n0 = wn * 16 + nt * 8 + 2 * t;
        bias2[nt][0] = smf[BH2O_OFF + n0]; bias2[nt][1] = smf[BH2O_OFF + n0 + 1];
    }

    const uint32_t* W1p  = g_W1  + (w * 2) * 128 + lane * 4;   // +kk*2048, p-> +128
    const uint32_t* W2p  = g_W2  + (w * 2) * 128 + lane * 4;
    const uint32_t* Wo1p = g_Wo1 + wn * 128 + lane * 4;        // +kk*512
    const uint32_t* Wo2p = g_Wo2 + wn * 128 + lane * 4;

    float* outseq = out;
    float* hfin = out + (size_t)T_STEPS * B_SIZE * DOUT;

    for (int ts = 0; ts < T_STEPS; ++ts) {
        // ---- stage x split ----
        const float* xt = x + ((size_t)ts * B_SIZE + gbase) * DIN;
        for (int i = tid; i < 64 * XKP; i += NTH) {
            int row = i >> 5, kp = i & 31;
            float2 v = *(const float2*)(xt + (size_t)row * DIN + kp * 2);
            uint32_t hi, lo;
            split2(v.x, v.y, hi, lo);
            X1[xidx(row, kp)] = hi;
            X2[xidx(row, kp)] = lo;
        }
        __syncthreads();   // [A]

        // ---- GEMM1 ----
        float acc[4][4][4];
        #pragma unroll
        for (int mt = 0; mt < 4; ++mt)
            #pragma unroll
            for (int nt = 0; nt < 4; ++nt) {
                acc[mt][nt][0] = bias1[nt][0]; acc[mt][nt][1] = bias1[nt][1];
                acc[mt][nt][2] = bias1[nt][0]; acc[mt][nt][3] = bias1[nt][1];
            }

        // pass 1: W1 with A1 and A2
        {
            uint4 B0 = *(const uint4*)(W1p);
            uint4 B1 = *(const uint4*)(W1p + 128);
            #pragma unroll 2
            for (int kk = 0; kk < 20; ++kk) {
                uint4 nB0 = *(const uint4*)(W1p + (kk + 1) * 2048);
                uint4 nB1 = *(const uint4*)(W1p + (kk + 1) * 2048 + 128);
                uint32_t a0, a1, a2, a3;
                if (kk < 4) {
                    const uint32_t kp0 = kk * 8;
                    #pragma unroll
                    for (int mt = 0; mt < 4; ++mt) {
                        LDSM4(a0, a1, a2, a3, AX(x1b, mt, kp0));
                        MMA(acc[mt][0], a0, a1, a2, a3, B0.x, B0.y);
                        MMA(acc[mt][1], a0, a1, a2, a3, B0.z, B0.w);
                        MMA(acc[mt][2], a0, a1, a2, a3, B1.x, B1.y);
                        MMA(acc[mt][3], a0, a1, a2, a3, B1.z, B1.w);
                        LDSM4(a0, a1, a2, a3, AX(x2b, mt, kp0));
                        MMA(acc[mt][0], a0, a1, a2, a3, B0.x, B0.y);
                        MMA(acc[mt][1], a0, a1, a2, a3, B0.z, B0.w);
                        MMA(acc[mt][2], a0, a1, a2, a3, B1.x, B1.y);
                        MMA(acc[mt][3], a0, a1, a2, a3, B1.z, B1.w);
                    }
                } else {
                    const uint32_t kp0 = (kk - 4) * 8;
                    #pragma unroll
                    for (int mt = 0; mt < 4; ++mt) {
                        LDSM4(a0, a1, a2, a3, AH(h1b, mt, kp0));
                        MMA(acc[mt][0], a0, a1, a2, a3, B0.x, B0.y);
                        MMA(acc[mt][1], a0, a1, a2, a3, B0.z, B0.w);
                        MMA(acc[mt][2], a0, a1, a2, a3, B1.x, B1.y);
                        MMA(acc[mt][3], a0, a1, a2, a3, B1.z, B1.w);
                        LDSM4(a0, a1, a2, a3, AH(h2b, mt, kp0));
                        MMA(acc[mt][0], a0, a1, a2, a3, B0.x, B0.y);
                        MMA(acc[mt][1], a0, a1, a2, a3, B0.z, B0.w);
                        MMA(acc[mt][2], a0, a1, a2, a3, B1.x, B1.y);
                        MMA(acc[mt][3], a0, a1, a2, a3, B1.z, B1.w);
                    }
                }
                B0 = nB0; B1 = nB1;
            }
        }
        // pass 2: W2 with A1
        {
            uint4 B0 = *(const uint4*)(W2p);
            uint4 B1 = *(const uint4*)(W2p + 128);
            #pragma unroll 2
            for (int kk = 0; kk < 20; ++kk) {
                uint4 nB0 = *(const uint4*)(W2p + (kk + 1) * 2048);
                uint4 nB1 = *(const uint4*)(W2p + (kk + 1) * 2048 + 128);
                uint32_t a0, a1, a2, a3;
                #pragma unroll
                for (int mt = 0; mt < 4; ++mt) {
                    if (kk < 4) { LDSM4(a0, a1, a2, a3, AX(x1b, mt, kk * 8)); }
                    else        { LDSM4(a0, a1, a2, a3, AH(h1b, mt, (kk - 4) * 8)); }
                    MMA(acc[mt][0], a0, a1, a2, a3, B0.x, B0.y);
                    MMA(acc[mt][1], a0, a1, a2, a3, B0.z, B0.w);
                    MMA(acc[mt][2], a0, a1, a2, a3, B1.x, B1.y);
                    MMA(acc[mt][3], a0, a1, a2, a3, B1.z, B1.w);
                }
                B0 = nB0; B1 = nB1;
            }
        }

        __syncthreads();   // [B]

        // ---- GEMM1 epilogue: fast tanh + fast split ----
        #pragma unroll
        for (int mt = 0; mt < 4; ++mt)
            #pragma unroll
            for (int nt = 0; nt < 4; ++nt) {
                float v0 = ftanh(acc[mt][nt][0]), v1 = ftanh(acc[mt][nt][1]);
                float v2 = ftanh(acc[mt][nt][2]), v3 = ftanh(acc[mt][nt][3]);
                int kp = w * 16 + nt * 4 + t;
                int r0 = mt * 16 + g, r1 = r0 + 8;
                uint32_t hiA, loA, hiB, loB;
                split2(v0, v1, hiA, loA);
                split2(v2, v3, hiB, loB);
                H1[hidx(r0, kp)] = hiA;
                H1[hidx(r1, kp)] = hiB;
                H2[hidx(r0, kp)] = loA;
                H2[hidx(r1, kp)] = loB;
            }
        __syncthreads();   // [C]

        // ---- GEMM2 ----
        float acc2[2][2][4];
        #pragma unroll
        for (int mt = 0; mt < 2; ++mt)
            #pragma unroll
            for (int nt = 0; nt < 2; ++nt) {
                acc2[mt][nt][0] = bias2[nt][0]; acc2[mt][nt][1] = bias2[nt][1];
                acc2[mt][nt][2] = bias2[nt][0]; acc2[mt][nt][3] = bias2[nt][1];
            }
        {
            uint4 B0 = *(const uint4*)(Wo1p);
            #pragma unroll 2
            for (int kk = 0; kk < 16; ++kk) {
                uint4 nB0 = *(const uint4*)(Wo1p + (kk + 1) * 512);
                uint32_t a0, a1, a2, a3;
                #pragma unroll
                for (int mt = 0; mt < 2; ++mt) {
                    LDSM4(a0, a1, a2, a3, AH(h1b, (2 * mh + mt), kk * 8));
                    MMA(acc2[mt][0], a0, a1, a2, a3, B0.x, B0.y);
                    MMA(acc2[mt][1], a0, a1, a2, a3, B0.z, B0.w);
                    LDSM4(a0, a1, a2, a3, AH(h2b, (2 * mh + mt), kk * 8));
                    MMA(acc2[mt][0], a0, a1, a2, a3, B0.x, B0.y);
                    MMA(acc2[mt][1], a0, a1, a2, a3, B0.z, B0.w);
                }
                B0 = nB0;
            }
            B0 = *(const uint4*)(Wo2p);
            #pragma unroll 2
            for (int kk = 0; kk < 16; ++kk) {
                uint4 nB0 = *(const uint4*)(Wo2p + (kk + 1) * 512);
                uint32_t a0, a1, a2, a3;
                #pragma unroll
                for (int mt = 0; mt < 2; ++mt) {
                    LDSM4(a0, a1, a2, a3, AH(h1b, (2 * mh + mt), kk * 8));
                    MMA(acc2[mt][0], a0, a1, a2, a3, B0.x, B0.y);
                    MMA(acc2[mt][1], a0, a1, a2, a3, B0.z, B0.w);
                }
                B0 = nB0;
            }
        }
        #pragma unroll
        for (int mt = 0; mt < 2; ++mt)
            #pragma unroll
            for (int nt = 0; nt < 2; ++nt) {
                int n0 = wn * 16 + nt * 8 + 2 * t;
                int r0 = 32 * mh + 16 * mt + g, r1 = r0 + 8;
                smf[SMS_OFF + r0 * 68 + n0]     = ftanh(acc2[mt][nt][0]);
                smf[SMS_OFF + r0 * 68 + n0 + 1] = ftanh(acc2[mt][nt][1]);
                smf[SMS_OFF + r1 * 68 + n0]     = ftanh(acc2[mt][nt][2]);
                smf[SMS_OFF + r1 * 68 + n0 + 1] = ftanh(acc2[mt][nt][3]);
            }
        __syncthreads();   // [D]

        // ---- GEMM3 ----
        {
            const int row = tid >> 2, col = tid & 3;
            float a3 = smf[BFC_OFF + col];
            const float* mrow = &smf[SMS_OFF + row * 68];
            const float* wrow = &smf[WFC_OFF + col * 65];
            #pragma unroll 8
            for (int k = 0; k < DMID; ++k)
                a3 = fmaf(mrow[k], wrow[k], a3);
            outseq[((size_t)ts * B_SIZE + gbase + row) * DOUT + col] = a3;
        }
    }

    __syncthreads();
    // ---- h_final = H1 + H2 ----
    for (int i = tid; i < 64 * HKP; i += NTH) {
        int row = i >> 7, kp = i & 127;
        uint32_t w1 = H1[hidx(row, kp)], w2 = H2[hidx(row, kp)];
        float2 v;
        v.x = __uint_as_float(w1 << 16) + __uint_as_float(w2 << 16);
        v.y = __uint_as_float(w1 & 0xFFFF0000u) + __uint_as_float(w2 & 0xFFFF0000u);
        *(float2*)(hfin + (size_t)(gbase + row) * DH + kp * 2) = v;
    }
}

extern "C" void kernel_launch(void* const* d_in, const int* in_sizes, int n_in,
                              void* d_out, int out_size) {
    const float* x    = (const float*)d_in[0];
    const float* hc1  = (const float*)d_in[1];
    const float* Wi2h = (const float*)d_in[2];
    const float* bi2h = (const float*)d_in[3];
    const float* Wh2h = (const float*)d_in[4];
    const float* bh2h = (const float*)d_in[5];
    const float* Wh2o = (const float*)d_in[6];
    const float* bh2o = (const float*)d_in[7];
    const float* Wfc  = (const float*)d_in[8];
    const float* bfc  = (const float*)d_in[9];
    float* out = (float*)d_out;

    cudaFuncSetAttribute(rnn_kernel, cudaFuncAttributeMaxDynamicSharedMemorySize, SMEM_BYTES);

    prep_kernel<<<64, 256>>>(Wi2h, bi2h, Wh2h, bh2h, Wh2o);
    rnn_kernel<<<NCTAS, NTH, SMEM_BYTES>>>(x, hc1, Wfc, bh2o, bfc, out);
}

// round 9
// speedup vs baseline: 1.1176x; 1.0031x over previous
#include <cuda_runtime.h>
#include <cuda_bf16.h>
#include <cstdint>
#include <cstddef>

#define T_STEPS 16
#define B_SIZE  16384
#define DIN     64
#define DH      256
#define DMID    64
#define DOUT    4
#define M_CTA   64
#define NCTAS   (B_SIZE / M_CTA)   // 256
#define NTH     256

#define HKP 128   // h k-pairs per row
#define XKP 32    // x k-pairs per row

// SMEM word offsets
#define H1_OFF   0
#define H2_OFF   (H1_OFF + 64 * HKP)
#define X1_OFF   (H2_OFF + 64 * HKP)
#define X2_OFF   (X1_OFF + 64 * XKP)
#define SMS_OFF  (X2_OFF + 64 * XKP)      // mid f32 [64][68]
#define WFC_OFF  (SMS_OFF + 64 * 68)
#define BH2O_OFF (WFC_OFF + 4 * 65)
#define BFC_OFF  (BH2O_OFF + 64)
#define BSUM_OFF (BFC_OFF + 4)
#define SMEM_WORDS (BSUM_OFF + 256)
#define SMEM_BYTES (SMEM_WORDS * 4)

// Pre-packed weight fragments (u32 = 2 bf16), +1 kk pad for prefetch clamp safety
__device__ uint32_t g_W1[21 * 8 * 2 * 32 * 4];   // GEMM1 hi split [kk][w][p][lane][4]
__device__ uint32_t g_W2[21 * 8 * 2 * 32 * 4];   // GEMM1 lo split
__device__ uint32_t g_Wo1[17 * 4 * 32 * 4];      // GEMM2 hi split [kk][wn][lane][4]
__device__ uint32_t g_Wo2[17 * 4 * 32 * 4];
__device__ float g_bsum[DH];

__device__ __forceinline__ uint32_t pk(__nv_bfloat16 lo, __nv_bfloat16 hi) {
    return (uint32_t)__bfloat16_as_ushort(lo) | ((uint32_t)__bfloat16_as_ushort(hi) << 16);
}
__device__ __forceinline__ int hidx(int row, int kp) { return row * HKP + (kp ^ ((row & 7) << 2)); }
__device__ __forceinline__ int xidx(int row, int kp) { return row * XKP + (kp ^ ((row & 7) << 2)); }

// fast accurate tanh: 1 - 2/(e^{2x}+1); abs err ~1e-6, saturates correctly
__device__ __forceinline__ float ftanh(float x) {
    float t = __expf(2.0f * x);
    float r;
    asm("rcp.approx.f32 %0, %1;" : "=f"(r) : "f"(t + 1.0f));
    return fmaf(-2.0f, r, 1.0f);
}

// split (v0,v1) -> hi word (bf16x2) + lo residual word (bf16x2)
__device__ __forceinline__ void split2(float v0, float v1, uint32_t& hi, uint32_t& lo) {
    asm("cvt.rn.bf16x2.f32 %0, %1, %2;" : "=r"(hi) : "f"(v1), "f"(v0));
    float f0 = __uint_as_float(hi << 16);
    float f1 = __uint_as_float(hi & 0xFFFF0000u);
    float r0 = v0 - f0, r1 = v1 - f1;
    asm("cvt.rn.bf16x2.f32 %0, %1, %2;" : "=r"(lo) : "f"(r1), "f"(r0));
}

#define MMA(d, A0, A1_, A2_, A3_, b0, b1)                                         \
    asm volatile("mma.sync.aligned.m16n8k16.row.col.f32.bf16.bf16.f32 "           \
                 "{%0,%1,%2,%3},{%4,%5,%6,%7},{%8,%9},{%0,%1,%2,%3};"             \
                 : "+f"(d[0]), "+f"(d[1]), "+f"(d[2]), "+f"(d[3])                 \
                 : "r"(A0), "r"(A1_), "r"(A2_), "r"(A3_), "r"(b0), "r"(b1))

#define LDSM4(a0, a1, a2, a3, addr)                                               \
    asm volatile("ldmatrix.sync.aligned.m8n8.x4.shared.b16 {%0,%1,%2,%3}, [%4];"  \
                 : "=r"(a0), "=r"(a1), "=r"(a2), "=r"(a3) : "r"(addr))

#define AH(base, mt, kp0) ((base) + (mt) * (16 * HKP * 4) + (((((kp0) + kadd)) ^ sxor) << 2))
#define AX(base, mt, kp0) ((base) + (mt) * (16 * XKP * 4) + (((((kp0) + kadd)) ^ sxor) << 2))

__global__ void prep_kernel(const float* __restrict__ Wi2h,
                            const float* __restrict__ bi2h,
                            const float* __restrict__ Wh2h,
                            const float* __restrict__ bh2h,
                            const float* __restrict__ Wh2o) {
    const int stride = gridDim.x * blockDim.x;
    const int tid = blockIdx.x * blockDim.x + threadIdx.x;
    for (int i = tid; i < 20 * 8 * 2 * 32 * 4; i += stride) {
        int word = i & 3, lane = (i >> 2) & 31, p = (i >> 7) & 1, w = (i >> 8) & 7, kk = i >> 11;
        int gg = lane >> 2, tt = lane & 3;
        int n = w * 32 + p * 16 + ((word >> 1) ? 8 : 0) + gg;
        int k = kk * 16 + tt * 2 + ((word & 1) ? 8 : 0);
        float v0, v1;
        if (k < DIN) { v0 = Wi2h[n * DIN + k]; v1 = Wi2h[n * DIN + k + 1]; }
        else         { v0 = Wh2h[n * DH + k - DIN]; v1 = Wh2h[n * DH + k - DIN + 1]; }
        __nv_bfloat16 h0 = __float2bfloat16_rn(v0), h1 = __float2bfloat16_rn(v1);
        g_W1[i] = pk(h0, h1);
        g_W2[i] = pk(__float2bfloat16_rn(v0 - __bfloat162float(h0)),
                     __float2bfloat16_rn(v1 - __bfloat162float(h1)));
    }
    for (int i = tid; i < 16 * 4 * 32 * 4; i += stride) {
        int word = i & 3, lane = (i >> 2) & 31, wn = (i >> 7) & 3, kk = i >> 9;
        int gg = lane >> 2, tt = lane & 3;
        int n = wn * 16 + ((word >> 1) ? 8 : 0) + gg;
        int k = kk * 16 + tt * 2 + ((word & 1) ? 8 : 0);
        float v0 = Wh2o[n * DH + k], v1 = Wh2o[n * DH + k + 1];
        __nv_bfloat16 h0 = __float2bfloat16_rn(v0), h1 = __float2bfloat16_rn(v1);
        g_Wo1[i] = pk(h0, h1);
        g_Wo2[i] = pk(__float2bfloat16_rn(v0 - __bfloat162float(h0)),
                      __float2bfloat16_rn(v1 - __bfloat162float(h1)));
    }
    for (int i = tid; i < DH; i += stride) g_bsum[i] = bi2h[i] + bh2h[i];
}

__global__ void __launch_bounds__(NTH, 2)
rnn_kernel(const float* __restrict__ x,
           const float* __restrict__ hc1,
           const float* __restrict__ Wfc,
           const float* __restrict__ bh2o,
           const float* __restrict__ bfc,
           float* __restrict__ out) {
    extern __shared__ uint32_t sm[];
    float* smf = (float*)sm;
    uint32_t* H1 = sm + H1_OFF;
    uint32_t* H2 = sm + H2_OFF;
    uint32_t* X1 = sm + X1_OFF;
    uint32_t* X2 = sm + X2_OFF;

    const int tid = threadIdx.x, w = tid >> 5, lane = tid & 31;
    const int g = lane >> 2, t = lane & 3;
    const int wn = w & 3, mh = w >> 2;
    const int gbase = blockIdx.x * M_CTA;

    const int rowA = (lane & 7) + ((lane >> 3) & 1) * 8;
    const uint32_t kadd = (lane >> 4) * 4;
    const uint32_t sxor = (uint32_t)((lane & 7) << 2);

    const uint32_t h1b = (uint32_t)__cvta_generic_to_shared(H1 + rowA * HKP);
    const uint32_t h2b = (uint32_t)__cvta_generic_to_shared(H2 + rowA * HKP);
    const uint32_t x1b = (uint32_t)__cvta_generic_to_shared(X1 + rowA * XKP);
    const uint32_t x2b = (uint32_t)__cvta_generic_to_shared(X2 + rowA * XKP);

    { // constants
        int c = tid >> 6, k = tid & 63;
        smf[WFC_OFF + c * 65 + k] = Wfc[c * DMID + k];
        if (tid < DMID) smf[BH2O_OFF + tid] = bh2o[tid];
        if (tid < DOUT) smf[BFC_OFF + tid] = bfc[tid];
        smf[BSUM_OFF + tid] = g_bsum[tid];
    }
    // stage hc1 split into H1/H2
    for (int i = tid; i < 64 * HKP; i += NTH) {
        int row = i >> 7, kp = i & 127;
        float2 v = *(const float2*)(hc1 + (size_t)(gbase + row) * DH + kp * 2);
        uint32_t hi, lo;
        split2(v.x, v.y, hi, lo);
        H1[hidx(row, kp)] = hi;
        H2[hidx(row, kp)] = lo;
    }
    __syncthreads();

    float bias1[4][2], bias2[2][2];
    #pragma unroll
    for (int nt = 0; nt < 4; ++nt) {
        int n0 = w * 32 + nt * 8 + 2 * t;
        bias1[nt][0] = smf[BSUM_OFF + n0]; bias1[nt][1] = smf[BSUM_OFF + n0 + 1];
    }
    #pragma unroll
    for (int nt = 0; nt < 2; ++nt) {
        int n0 = wn * 16 + nt * 8 + 2 * t;
        bias2[nt][0] = smf[BH2O_OFF + n0]; bias2[nt][1] = smf[BH2O_OFF + n0 + 1];
    }

    const uint32_t* W1p  = g_W1  + (w * 2) * 128 + lane * 4;   // +kk*2048, p-> +128
    const uint32_t* W2p  = g_W2  + (w * 2) * 128 + lane * 4;
    const uint32_t* Wo1p = g_Wo1 + wn * 128 + lane * 4;        // +kk*512
    const uint32_t* Wo2p = g_Wo2 + wn * 128 + lane * 4;

    float* outseq = out;
    float* hfin = out + (size_t)T_STEPS * B_SIZE * DOUT;

    for (int ts = 0; ts < T_STEPS; ++ts) {
        // ---- stage x split ----
        const float* xt = x + ((size_t)ts * B_SIZE + gbase) * DIN;
        for (int i = tid; i < 64 * XKP; i += NTH) {
            int row = i >> 5, kp = i & 31;
            float2 v = *(const float2*)(xt + (size_t)row * DIN + kp * 2);
            uint32_t hi, lo;
            split2(v.x, v.y, hi, lo);
            X1[xidx(row, kp)] = hi;
            X2[xidx(row, kp)] = lo;
        }
        __syncthreads();   // [A]

        // ---- GEMM1 ----
        float acc[4][4][4];
        #pragma unroll
        for (int mt = 0; mt < 4; ++mt)
            #pragma unroll
            for (int nt = 0; nt < 4; ++nt) {
                acc[mt][nt][0] = bias1[nt][0]; acc[mt][nt][1] = bias1[nt][1];
                acc[mt][nt][2] = bias1[nt][0]; acc[mt][nt][3] = bias1[nt][1];
            }

        // pass 1: W1 with A1 and A2
        {
            uint4 B0 = *(const uint4*)(W1p);
            uint4 B1 = *(const uint4*)(W1p + 128);
            #pragma unroll 2
            for (int kk = 0; kk < 20; ++kk) {
                uint4 nB0 = *(const uint4*)(W1p + (kk + 1) * 2048);
                uint4 nB1 = *(const uint4*)(W1p + (kk + 1) * 2048 + 128);
                uint32_t a0, a1, a2, a3;
                if (kk < 4) {
                    const uint32_t kp0 = kk * 8;
                    #pragma unroll
                    for (int mt = 0; mt < 4; ++mt) {
                        LDSM4(a0, a1, a2, a3, AX(x1b, mt, kp0));
                        MMA(acc[mt][0], a0, a1, a2, a3, B0.x, B0.y);
                        MMA(acc[mt][1], a0, a1, a2, a3, B0.z, B0.w);
                        MMA(acc[mt][2], a0, a1, a2, a3, B1.x, B1.y);
                        MMA(acc[mt][3], a0, a1, a2, a3, B1.z, B1.w);
                        LDSM4(a0, a1, a2, a3, AX(x2b, mt, kp0));
                        MMA(acc[mt][0], a0, a1, a2, a3, B0.x, B0.y);
                        MMA(acc[mt][1], a0, a1, a2, a3, B0.z, B0.w);
                        MMA(acc[mt][2], a0, a1, a2, a3, B1.x, B1.y);
                        MMA(acc[mt][3], a0, a1, a2, a3, B1.z, B1.w);
                    }
                } else {
                    const uint32_t kp0 = (kk - 4) * 8;
                    #pragma unroll
                    for (int mt = 0; mt < 4; ++mt) {
                        LDSM4(a0, a1, a2, a3, AH(h1b, mt, kp0));
                        MMA(acc[mt][0], a0, a1, a2, a3, B0.x, B0.y);
                        MMA(acc[mt][1], a0, a1, a2, a3, B0.z, B0.w);
                        MMA(acc[mt][2], a0, a1, a2, a3, B1.x, B1.y);
                        MMA(acc[mt][3], a0, a1, a2, a3, B1.z, B1.w);
                        LDSM4(a0, a1, a2, a3, AH(h2b, mt, kp0));
                        MMA(acc[mt][0], a0, a1, a2, a3, B0.x, B0.y);
                        MMA(acc[mt][1], a0, a1, a2, a3, B0.z, B0.w);
                        MMA(acc[mt][2], a0, a1, a2, a3, B1.x, B1.y);
                        MMA(acc[mt][3], a0, a1, a2, a3, B1.z, B1.w);
                    }
                }
                B0 = nB0; B1 = nB1;
            }
        }
        // pass 2: W2 with A1
        {
            uint4 B0 = *(const uint4*)(W2p);
            uint4 B1 = *(const uint4*)(W2p + 128);
            #pragma unroll 2
            for (int kk = 0; kk < 20; ++kk) {
                uint4 nB0 = *(const uint4*)(W2p + (kk + 1) * 2048);
                uint4 nB1 = *(const uint4*)(W2p + (kk + 1) * 2048 + 128);
                uint32_t a0, a1, a2, a3;
                #pragma unroll
                for (int mt = 0; mt < 4; ++mt) {
                    if (kk < 4) { LDSM4(a0, a1, a2, a3, AX(x1b, mt, kk * 8)); }
                    else        { LDSM4(a0, a1, a2, a3, AH(h1b, mt, (kk - 4) * 8)); }
                    MMA(acc[mt][0], a0, a1, a2, a3, B0.x, B0.y);
                    MMA(acc[mt][1], a0, a1, a2, a3, B0.z, B0.w);
                    MMA(acc[mt][2], a0, a1, a2, a3, B1.x, B1.y);
                    MMA(acc[mt][3], a0, a1, a2, a3, B1.z, B1.w);
                }
                B0 = nB0; B1 = nB1;
            }
        }

        __syncthreads();   // [B]

        // ---- GEMM1 epilogue: fast tanh + fast split ----
        #pragma unroll
        for (int mt = 0; mt < 4; ++mt)
            #pragma unroll
            for (int nt = 0; nt < 4; ++nt) {
                float v0 = ftanh(acc[mt][nt][0]), v1 = ftanh(acc[mt][nt][1]);
                float v2 = ftanh(acc[mt][nt][2]), v3 = ftanh(acc[mt][nt][3]);
                int kp = w * 16 + nt * 4 + t;
                int r0 = mt * 16 + g, r1 = r0 + 8;
                uint32_t hiA, loA, hiB, loB;
                split2(v0, v1, hiA, loA);
                split2(v2, v3, hiB, loB);
                H1[hidx(r0, kp)] = hiA;
                H1[hidx(r1, kp)] = hiB;
                H2[hidx(r0, kp)] = loA;
                H2[hidx(r1, kp)] = loB;
            }
        __syncthreads();   // [C]

        // ---- GEMM2 ----
        float acc2[2][2][4];
        #pragma unroll
        for (int mt = 0; mt < 2; ++mt)
            #pragma unroll
            for (int nt = 0; nt < 2; ++nt) {
                acc2[mt][nt][0] = bias2[nt][0]; acc2[mt][nt][1] = bias2[nt][1];
                acc2[mt][nt][2] = bias2[nt][0]; acc2[mt][nt][3] = bias2[nt][1];
            }
        {
            uint4 B0 = *(const uint4*)(Wo1p);
            #pragma unroll 2
            for (int kk = 0; kk < 16; ++kk) {
                uint4 nB0 = *(const uint4*)(Wo1p + (kk + 1) * 512);
                uint32_t a0, a1, a2, a3;
                #pragma unroll
                for (int mt = 0; mt < 2; ++mt) {
                    LDSM4(a0, a1, a2, a3, AH(h1b, (2 * mh + mt), kk * 8));
                    MMA(acc2[mt][0], a0, a1, a2, a3, B0.x, B0.y);
                    MMA(acc2[mt][1], a0, a1, a2, a3, B0.z, B0.w);
                    LDSM4(a0, a1, a2, a3, AH(h2b, (2 * mh + mt), kk * 8));
                    MMA(acc2[mt][0], a0, a1, a2, a3, B0.x, B0.y);
                    MMA(acc2[mt][1], a0, a1, a2, a3, B0.z, B0.w);
                }
                B0 = nB0;
            }
            B0 = *(const uint4*)(Wo2p);
            #pragma unroll 2
            for (int kk = 0; kk < 16; ++kk) {
                uint4 nB0 = *(const uint4*)(Wo2p + (kk + 1) * 512);
                uint32_t a0, a1, a2, a3;
                #pragma unroll
                for (int mt = 0; mt < 2; ++mt) {
                    LDSM4(a0, a1, a2, a3, AH(h1b, (2 * mh + mt), kk * 8));
                    MMA(acc2[mt][0], a0, a1, a2, a3, B0.x, B0.y);
                    MMA(acc2[mt][1], a0, a1, a2, a3, B0.z, B0.w);
                }
                B0 = nB0;
            }
        }
        #pragma unroll
        for (int mt = 0; mt < 2; ++mt)
            #pragma unroll
            for (int nt = 0; nt < 2; ++nt) {
                int n0 = wn * 16 + nt * 8 + 2 * t;
                int r0 = 32 * mh + 16 * mt + g, r1 = r0 + 8;
                smf[SMS_OFF + r0 * 68 + n0]     = ftanh(acc2[mt][nt][0]);
                smf[SMS_OFF + r0 * 68 + n0 + 1] = ftanh(acc2[mt][nt][1]);
                smf[SMS_OFF + r1 * 68 + n0]     = ftanh(acc2[mt][nt][2]);
                smf[SMS_OFF + r1 * 68 + n0 + 1] = ftanh(acc2[mt][nt][3]);
            }
        __syncthreads();   // [D]

        // ---- GEMM3 ----
        {
            const int row = tid >> 2, col = tid & 3;
            float a3 = smf[BFC_OFF + col];
            const float* mrow = &smf[SMS_OFF + row * 68];
            const float* wrow = &smf[WFC_OFF + col * 65];
            #pragma unroll 8
            for (int k = 0; k < DMID; ++k)
                a3 = fmaf(mrow[k], wrow[k], a3);
            outseq[((size_t)ts * B_SIZE + gbase + row) * DOUT + col] = a3;
        }
    }

    __syncthreads();
    // ---- h_final = H1 + H2 ----
    for (int i = tid; i < 64 * HKP; i += NTH) {
        int row = i >> 7, kp = i & 127;
        uint32_t w1 = H1[hidx(row, kp)], w2 = H2[hidx(row, kp)];
        float2 v;
        v.x = __uint_as_float(w1 << 16) + __uint_as_float(w2 << 16);
        v.y = __uint_as_float(w1 & 0xFFFF0000u) + __uint_as_float(w2 & 0xFFFF0000u);
        *(float2*)(hfin + (size_t)(gbase + row) * DH + kp * 2) = v;
    }
}

extern "C" void kernel_launch(void* const* d_in, const int* in_sizes, int n_in,
                              void* d_out, int out_size) {
    const float* x    = (const float*)d_in[0];
    const float* hc1  = (const float*)d_in[1];
    const float* Wi2h = (const float*)d_in[2];
    const float* bi2h = (const float*)d_in[3];
    const float* Wh2h = (const float*)d_in[4];
    const float* bh2h = (const float*)d_in[5];
    const float* Wh2o = (const float*)d_in[6];
    const float* bh2o = (const float*)d_in[7];
    const float* Wfc  = (const float*)d_in[8];
    const float* bfc  = (const float*)d_in[9];
    float* out = (float*)d_out;

    cudaFuncSetAttribute(rnn_kernel, cudaFuncAttributeMaxDynamicSharedMemorySize, SMEM_BYTES);

    prep_kernel<<<64, 256>>>(Wi2h, bi2h, Wh2h, bh2h, Wh2o);
    rnn_kernel<<<NCTAS, NTH, SMEM_BYTES>>>(x, hc1, Wfc, bh2o, bfc, out);
}